// round 15
// baseline (speedup 1.0000x reference)
#include <cuda_runtime.h>
#include <math.h>

#define H   1032
#define INW 2064
#define G3  3096
#define SL  8192
#define V   50257

// d_out layout: output(V), attn_context(H), hidden(H), attn_w(S)
#define OUT_CTX    50257
#define OUT_HID    51289
#define OUT_ATTNW  52321

// scratch
__device__ float g_gx[G3];
__device__ float g_gh[G3];
__device__ __align__(16) float g_hnew[H];
__device__ __align__(16) float g_v[H];
__device__ float g_c0;
__device__ float g_scores[SL];
__device__ float g_ctx[H];

__device__ __forceinline__ float dot4(float4 a, float4 b) {
    return a.x * b.x + a.y * b.y + a.z * b.z + a.w * b.w;
}

__device__ __forceinline__ float warp_red(float s) {
    #pragma unroll
    for (int o = 16; o; o >>= 1) s += __shfl_xor_sync(0xffffffffu, s, o);
    return s;
}

// ---- mbarrier / bulk-copy helpers ----
__device__ __forceinline__ unsigned smem_u32(const void* p) {
    return (unsigned)__cvta_generic_to_shared(p);
}
#define MBAR_INIT(addr, cnt) \
    asm volatile("mbarrier.init.shared.b64 [%0], %1;" :: "r"(addr), "r"(cnt) : "memory")
#define MBAR_EXPECT_TX(addr, bytes) \
    asm volatile("mbarrier.arrive.expect_tx.shared.b64 _, [%0], %1;" :: "r"(addr), "r"(bytes) : "memory")
#define MBAR_WAIT(addr, ph) \
    asm volatile("{\n\t.reg .pred P;\n\tWL%=:\n\t" \
                 "mbarrier.try_wait.parity.acquire.cta.shared::cta.b64 P, [%0], %1, 0x989680;\n\t" \
                 "@P bra.uni WD%=;\n\tbra.uni WL%=;\n\tWD%=:\n\t}" \
                 :: "r"(addr), "r"(ph) : "memory")
#define BULK_G2S(dst, src, bytes, mbar) \
    asm volatile("cp.async.bulk.shared::cluster.global.mbarrier::complete_tx::bytes [%0], [%1], %2, [%3];" \
                 :: "r"(dst), "l"(src), "r"(bytes), "r"(mbar) : "memory")

// 2064-B chunk dot (129 float4); lane-sliced
__device__ __forceinline__ float chunk_dot_129(const float4* __restrict__ b4,
                                               const float4* __restrict__ x4, int lane) {
    float s0 = 0.f, s1 = 0.f, s2 = 0.f, s3 = 0.f;
    s0 += dot4(b4[lane +  0], x4[lane +  0]);
    s1 += dot4(b4[lane + 32], x4[lane + 32]);
    s2 += dot4(b4[lane + 64], x4[lane + 64]);
    s3 += dot4(b4[lane + 96], x4[lane + 96]);
    if (lane < 1) s0 += dot4(b4[128], x4[128]);
    return (s0 + s1) + (s2 + s3);
}

// ---- R2-style row dots (small LDG kernels) ----
__device__ __forceinline__ float row_dot_516(const float4* __restrict__ w4,
                                             const float4* __restrict__ x4, int lane) {
    float s0 = 0.f, s1 = 0.f, s2 = 0.f, s3 = 0.f;
    #pragma unroll
    for (int i = 0; i < 16; i += 4) {
        float4 a = w4[lane + 32 * (i + 0)];
        float4 b = w4[lane + 32 * (i + 1)];
        float4 c = w4[lane + 32 * (i + 2)];
        float4 d = w4[lane + 32 * (i + 3)];
        s0 += dot4(a, x4[lane + 32 * (i + 0)]);
        s1 += dot4(b, x4[lane + 32 * (i + 1)]);
        s2 += dot4(c, x4[lane + 32 * (i + 2)]);
        s3 += dot4(d, x4[lane + 32 * (i + 3)]);
    }
    if (lane < 4) s0 += dot4(w4[512 + lane], x4[512 + lane]);
    return (s0 + s1) + (s2 + s3);
}

__device__ __forceinline__ float row_dot_258(const float4* __restrict__ w4,
                                             const float4* __restrict__ x4, int lane) {
    float s0 = 0.f, s1 = 0.f, s2 = 0.f, s3 = 0.f;
    #pragma unroll
    for (int i = 0; i < 8; i += 4) {
        float4 a = w4[lane + 32 * (i + 0)];
        float4 b = w4[lane + 32 * (i + 1)];
        float4 c = w4[lane + 32 * (i + 2)];
        float4 d = w4[lane + 32 * (i + 3)];
        s0 += dot4(a, x4[lane + 32 * (i + 0)]);
        s1 += dot4(b, x4[lane + 32 * (i + 1)]);
        s2 += dot4(c, x4[lane + 32 * (i + 2)]);
        s3 += dot4(d, x4[lane + 32 * (i + 3)]);
    }
    if (lane < 2) s0 += dot4(w4[256 + lane], x4[256 + lane]);
    return (s0 + s1) + (s2 + s3);
}

#define IH_BLOCKS 387   // 3096 rows / 8 warps

// ---------------- K1: gates (R2 config)
__global__ void k_gates(const int* __restrict__ word, const float* __restrict__ lctx,
                        const float* __restrict__ hprev, const float* __restrict__ emb,
                        const float* __restrict__ W_ih, const float* __restrict__ W_hh,
                        const float* __restrict__ b_ih, const float* __restrict__ b_hh) {
    __shared__ __align__(16) float sx[INW];
    int lane = threadIdx.x & 31;
    int wib  = threadIdx.x >> 5;
    if (blockIdx.x < IH_BLOCKS) {
        const float* erow = emb + (size_t)word[0] * H;
        for (int i = threadIdx.x; i < INW; i += blockDim.x)
            sx[i] = (i < H) ? erow[i] : lctx[i - H];
        __syncthreads();
        int row = blockIdx.x * 8 + wib;
        float s = row_dot_516((const float4*)(W_ih + (size_t)row * INW),
                              (const float4*)sx, lane);
        s = warp_red(s);
        if (lane == 0) g_gx[row] = s + b_ih[row];
    } else {
        for (int i = threadIdx.x; i < H; i += blockDim.x) sx[i] = hprev[i];
        __syncthreads();
        int row = (blockIdx.x - IH_BLOCKS) * 8 + wib;
        float s = row_dot_258((const float4*)(W_hh + (size_t)row * H),
                              (const float4*)sx, lane);
        s = warp_red(s);
        if (lane == 0) g_gh[row] = s + b_hh[row];
    }
}

// ---------------- K2: GRU combine
__global__ void k_gru(const float* __restrict__ hprev, const float* __restrict__ b_a,
                      float* __restrict__ d_out) {
    __shared__ float acc;
    int tid = threadIdx.x;
    if (tid == 0) acc = 0.f;
    __syncthreads();
    float part = 0.f;
    for (int i = tid; i < H; i += blockDim.x) {
        float r = 1.f / (1.f + expf(-(g_gx[i] + g_gh[i])));
        float z = 1.f / (1.f + expf(-(g_gx[i + H] + g_gh[i + H])));
        float n = tanhf(g_gx[i + 2 * H] + r * g_gh[i + 2 * H]);
        float h = hprev[i];
        float hn = (1.f - z) * n + z * h;
        g_hnew[i] = hn;
        d_out[OUT_HID + i] = hn;
        g_v[i] = 0.f;
        g_ctx[i] = 0.f;
        part += b_a[i] * hn;
    }
    part = warp_red(part);
    if ((tid & 31) == 0) atomicAdd(&acc, part);
    __syncthreads();
    if (tid == 0) g_c0 = acc;
}

// ---------------- K3: v = W_a^T h_new
__global__ void k_va(const float* __restrict__ W_a) {
    int k = blockIdx.x * 128 + threadIdx.x;
    int j0 = blockIdx.y * 129;
    if (k >= H) return;
    float p0 = 0.f, p1 = 0.f, p2 = 0.f;
    int j = j0;
    #pragma unroll 3
    for (int u = 0; u < 43; ++u, j += 3) {
        p0 += W_a[(size_t)(j + 0) * H + k] * g_hnew[j + 0];
        p1 += W_a[(size_t)(j + 1) * H + k] * g_hnew[j + 1];
        p2 += W_a[(size_t)(j + 2) * H + k] * g_hnew[j + 2];
    }
    atomicAdd(&g_v[k], p0 + p1 + p2);
}

// ---- bulk-pipeline geometry ----
#define NB        592            // 4 blocks/SM, one wave
#define TILE_F4   1032           // 16512 B per stage buffer

// ---------------- K4: scores via cp.async.bulk (tile = 4 enc rows = 16512 B)
#define SC_TT   (SL / 4)         // 2048 tiles
#define SC_TPB  4                // ceil(2048/592)
__global__ __launch_bounds__(256) void k_scores(const float* __restrict__ enc) {
    __shared__ __align__(16) float sv[H];
    __shared__ __align__(16) float4 buf[2][TILE_F4];
    __shared__ __align__(8) unsigned long long mbar[2];
    __shared__ float part[8];
    int tid = threadIdx.x, lane = tid & 31, wib = tid >> 5;

    if (tid == 0) { MBAR_INIT(smem_u32(&mbar[0]), 1); MBAR_INIT(smem_u32(&mbar[1]), 1); }
    for (int i = tid; i < H; i += 256) sv[i] = g_v[i];
    __syncthreads();

    int g0 = blockIdx.x * SC_TPB;
    int NT = SC_TT - g0; if (NT > SC_TPB) NT = SC_TPB; if (NT < 0) NT = 0;

    if (tid == 0) {
        #pragma unroll
        for (int i = 0; i < 2; ++i) {
            if (i < NT) {
                int r = (g0 + i) * 4;
                MBAR_EXPECT_TX(smem_u32(&mbar[i]), 4 * 4128u);
                BULK_G2S(smem_u32(&buf[i][0]), enc + (size_t)r * H, 4 * 4128u, smem_u32(&mbar[i]));
            }
        }
    }

    int row = wib >> 1, hf = wib & 1;
    for (int t = 0; t < NT; ++t) {
        int s = t & 1;
        MBAR_WAIT(smem_u32(&mbar[s]), (t >> 1) & 1);
        int r0 = (g0 + t) * 4;
        float p = chunk_dot_129(&buf[s][row * 258 + hf * 129],
                                (const float4*)sv + hf * 129, lane);
        p = warp_red(p);
        if (lane == 0) part[wib] = p;
        __syncthreads();
        if (tid == 0 && t + 2 < NT) {
            int r2 = (g0 + t + 2) * 4;
            MBAR_EXPECT_TX(smem_u32(&mbar[s]), 4 * 4128u);
            BULK_G2S(smem_u32(&buf[s][0]), enc + (size_t)r2 * H, 4 * 4128u, smem_u32(&mbar[s]));
        }
        if (tid < 4)
            g_scores[r0 + tid] = part[2 * tid] + part[2 * tid + 1] + g_c0;
        __syncthreads();
    }
}

// ---------------- K5: softmax over 8192 scores -> attn_w in d_out
__global__ void k_softmax(float* __restrict__ d_out) {
    __shared__ float red[32];
    int tid = threadIdx.x;
    float vals[8];
    float m = -1e30f;
    #pragma unroll
    for (int u = 0; u < 8; u++) { vals[u] = g_scores[tid + u * 1024]; m = fmaxf(m, vals[u]); }
    #pragma unroll
    for (int o = 16; o; o >>= 1) m = fmaxf(m, __shfl_xor_sync(0xffffffffu, m, o));
    if ((tid & 31) == 0) red[tid >> 5] = m;
    __syncthreads();
    if (tid < 32) {
        float t = red[tid];
        #pragma unroll
        for (int o = 16; o; o >>= 1) t = fmaxf(t, __shfl_xor_sync(0xffffffffu, t, o));
        if (tid == 0) red[0] = t;
    }
    __syncthreads();
    m = red[0];
    __syncthreads();
    float ssum = 0.f;
    #pragma unroll
    for (int u = 0; u < 8; u++) { vals[u] = expf(vals[u] - m); ssum += vals[u]; }
    ssum = warp_red(ssum);
    if ((tid & 31) == 0) red[tid >> 5] = ssum;
    __syncthreads();
    if (tid < 32) {
        float t = red[tid];
        t = warp_red(t);
        if (tid == 0) red[0] = t;
    }
    __syncthreads();
    float inv = 1.f / red[0];
    #pragma unroll
    for (int u = 0; u < 8; u++)
        d_out[OUT_ATTNW + tid + u * 1024] = vals[u] * inv;
}

// ---------------- K6: context (R2 config)
__global__ void k_context(const float* __restrict__ enc, const float* __restrict__ d_out) {
    int s0 = blockIdx.x * 64;
    int tid = threadIdx.x;
    float a0 = 0, a1 = 0, a2 = 0, a3 = 0, a4 = 0;
    for (int s = s0; s < s0 + 64; ++s) {
        float w = __ldg(&d_out[OUT_ATTNW + s]);
        const float* row = enc + (size_t)s * H;
        a0 += w * row[tid];
        a1 += w * row[tid + 256];
        a2 += w * row[tid + 512];
        a3 += w * row[tid + 768];
        if (tid < 8) a4 += w * row[tid + 1024];
    }
    atomicAdd(&g_ctx[tid], a0);
    atomicAdd(&g_ctx[tid + 256], a1);
    atomicAdd(&g_ctx[tid + 512], a2);
    atomicAdd(&g_ctx[tid + 768], a3);
    if (tid < 8) atomicAdd(&g_ctx[tid + 1024], a4);
}

// ---------------- K7: logits via cp.async.bulk (tile = 2 W_out rows = 16512 B; join fused)
#define KO_TT   ((V + 1) / 2)    // 25129 tiles
#define KO_TPB  43               // ceil(25129/592)
__global__ __launch_bounds__(256) void k_out(const float* __restrict__ W_out,
                                             const float* __restrict__ b_out,
                                             float* __restrict__ d_out) {
    __shared__ __align__(16) float sj[INW];
    __shared__ __align__(16) float4 buf[2][TILE_F4];
    __shared__ __align__(8) unsigned long long mbar[2];
    __shared__ float part[8];
    int tid = threadIdx.x, lane = tid & 31, wib = tid >> 5;

    if (tid == 0) { MBAR_INIT(smem_u32(&mbar[0]), 1); MBAR_INIT(smem_u32(&mbar[1]), 1); }
    for (int i = tid; i < H; i += 256) {
        sj[i] = g_hnew[i];
        float c = g_ctx[i];
        sj[H + i] = c;
        if (blockIdx.x == 0) d_out[OUT_CTX + i] = c;
    }
    __syncthreads();

    int g0 = blockIdx.x * KO_TPB;
    int NT = KO_TT - g0; if (NT > KO_TPB) NT = KO_TPB; if (NT < 0) NT = 0;

    if (tid == 0) {
        #pragma unroll
        for (int i = 0; i < 2; ++i) {
            if (i < NT) {
                int r = (g0 + i) * 2;
                int nr = V - r; if (nr > 2) nr = 2;
                unsigned nb = (unsigned)nr * 8256u;
                MBAR_EXPECT_TX(smem_u32(&mbar[i]), nb);
                BULK_G2S(smem_u32(&buf[i][0]), W_out + (size_t)r * INW, nb, smem_u32(&mbar[i]));
            }
        }
    }

    int row = wib >> 2, q = wib & 3;
    for (int t = 0; t < NT; ++t) {
        int s = t & 1;
        MBAR_WAIT(smem_u32(&mbar[s]), (t >> 1) & 1);
        int r0 = (g0 + t) * 2;
        int nrows = V - r0; if (nrows > 2) nrows = 2;
        if (row < nrows) {
            float p = chunk_dot_129(&buf[s][row * 516 + q * 129],
                                    (const float4*)sj + q * 129, lane);
            p = warp_red(p);
            if (lane == 0) part[wib] = p;
        }
        __syncthreads();
        if (tid == 0 && t + 2 < NT) {
            int r2 = (g0 + t + 2) * 2;
            int nr = V - r2; if (nr > 2) nr = 2;
            unsigned nb = (unsigned)nr * 8256u;
            MBAR_EXPECT_TX(smem_u32(&mbar[s]), nb);
            BULK_G2S(smem_u32(&buf[s][0]), W_out + (size_t)r2 * INW, nb, smem_u32(&mbar[s]));
        }
        if (tid < nrows) {
            int rg = r0 + tid;
            float ssum = part[4 * tid] + part[4 * tid + 1] + part[4 * tid + 2] + part[4 * tid + 3];
            d_out[rg] = ssum + b_out[rg];
        }
        __syncthreads();
    }
}

// ---------------- K8: log-softmax in place
__global__ void k_lsefinal(float* __restrict__ d_out) {
    __shared__ float red[32];
    __shared__ float s_lse;
    int tid = threadIdx.x;                    // 1024
    float m = -1e30f;
    for (int i = tid; i < V; i += 1024) m = fmaxf(m, d_out[i]);
    #pragma unroll
    for (int o = 16; o; o >>= 1) m = fmaxf(m, __shfl_xor_sync(0xffffffffu, m, o));
    if ((tid & 31) == 0) red[tid >> 5] = m;
    __syncthreads();
    if (tid < 32) {
        float t = red[tid];
        #pragma unroll
        for (int o = 16; o; o >>= 1) t = fmaxf(t, __shfl_xor_sync(0xffffffffu, t, o));
        if (tid == 0) red[0] = t;
    }
    __syncthreads();
    m = red[0];
    __syncthreads();
    float sum = 0.f;
    for (int i = tid; i < V; i += 1024) sum += expf(d_out[i] - m);
    sum = warp_red(sum);
    if ((tid & 31) == 0) red[tid >> 5] = sum;
    __syncthreads();
    if (tid < 32) {
        float t = red[tid];
        t = warp_red(t);
        if (tid == 0) s_lse = m + logf(t);
    }
    __syncthreads();
    float lse = s_lse;
    for (int i = tid; i < V; i += 1024) d_out[i] -= lse;
}

extern "C" void kernel_launch(void* const* d_in, const int* in_sizes, int n_in,
                              void* d_out, int out_size) {
    const int*   word  = (const int*)  d_in[0];
    const float* lctx  = (const float*)d_in[1];
    const float* hprev = (const float*)d_in[2];
    const float* enc   = (const float*)d_in[3];
    const float* emb   = (const float*)d_in[4];
    const float* W_ih  = (const float*)d_in[5];
    const float* W_hh  = (const float*)d_in[6];
    const float* b_ih  = (const float*)d_in[7];
    const float* b_hh  = (const float*)d_in[8];
    const float* W_a   = (const float*)d_in[9];
    const float* b_a   = (const float*)d_in[10];
    const float* W_out = (const float*)d_in[11];
    const float* b_out = (const float*)d_in[12];
    float* out = (float*)d_out;

    k_gates   <<<2 * IH_BLOCKS, 256>>>(word, lctx, hprev, emb, W_ih, W_hh, b_ih, b_hh);
    k_gru     <<<1, 1024>>>(hprev, b_a, out);
    k_va      <<<dim3(9, 8), 128>>>(W_a);
    k_scores  <<<NB, 256>>>(enc);
    k_softmax <<<1, 1024>>>(out);
    k_context <<<128, 256>>>(enc, out);
    k_out     <<<NB, 256>>>(W_out, b_out, out);
    k_lsefinal<<<1, 1024>>>(out);
}